// round 15
// baseline (speedup 1.0000x reference)
#include <cuda_runtime.h>
#include <cuda_bf16.h>
#include <cstdint>
#include <math.h>

// ---------------------------------------------------------------------------
// Problem constants: B=4, S=2048, HID=2048, NH=16, NKV=4, HD=128.
// ---------------------------------------------------------------------------
#define B_    4
#define S_    2048
#define HID_  2048
#define NH_   16
#define NKV_  4
#define HD_   128
#define QSZ   (NH_ * HD_)          // 2048
#define KVSZ  (NKV_ * HD_)         // 512
#define QKVN  (QSZ + 2 * KVSZ)     // 3072
#define TOK   (B_ * S_)            // 8192

// Scratch (device globals; no allocs allowed)
__device__ __align__(16) float          g_qkv[(size_t)TOK * QKVN];
__device__ __align__(16) __nv_bfloat16  g_hid_h[(size_t)TOK * HID_];
__device__ __align__(16) __nv_bfloat16  g_hid_l[(size_t)TOK * HID_];
__device__ __align__(16) __nv_bfloat16  g_attn_h[(size_t)TOK * HID_];
__device__ __align__(16) __nv_bfloat16  g_attn_l[(size_t)TOK * HID_];
__device__ __align__(16) __nv_bfloat16  g_wqkv_h[(size_t)QKVN * HID_];  // [N][K]
__device__ __align__(16) __nv_bfloat16  g_wqkv_l[(size_t)QKVN * HID_];
__device__ __align__(16) __nv_bfloat16  g_wo_h[(size_t)HID_ * HID_];    // [N][K]
__device__ __align__(16) __nv_bfloat16  g_wo_l[(size_t)HID_ * HID_];
__device__ __align__(16) __nv_bfloat16  g_qkvb_h[(size_t)TOK * QKVN];   // rope'd q,k
__device__ __align__(16) __nv_bfloat16  g_qkvb_l[(size_t)TOK * QKVN];
// V^T pre-transposed: [b][kvh][hd][S]
__device__ __align__(16) __nv_bfloat16  g_vt_h[(size_t)B_ * NKV_ * HD_ * S_];
__device__ __align__(16) __nv_bfloat16  g_vt_l[(size_t)B_ * NKV_ * HD_ * S_];

// ---------------------------------------------------------------------------
// Helpers
// ---------------------------------------------------------------------------
__device__ __forceinline__ uint32_t smem_u32(const void* p) {
    uint32_t a;
    asm("{ .reg .u64 t; cvta.to.shared.u64 t, %1; cvt.u32.u64 %0, t; }"
        : "=r"(a) : "l"(p));
    return a;
}
__device__ __forceinline__ void ldsm_x4(uint32_t addr, uint32_t& r0, uint32_t& r1,
                                        uint32_t& r2, uint32_t& r3) {
    asm volatile("ldmatrix.sync.aligned.m8n8.x4.shared.b16 {%0,%1,%2,%3}, [%4];"
                 : "=r"(r0), "=r"(r1), "=r"(r2), "=r"(r3) : "r"(addr));
}
__device__ __forceinline__ void mma_bf16(float* d, const uint32_t* a,
                                         const uint32_t* b) {
    asm volatile(
        "mma.sync.aligned.m16n8k16.row.col.f32.bf16.bf16.f32 "
        "{%0,%1,%2,%3}, {%4,%5,%6,%7}, {%8,%9}, {%0,%1,%2,%3};"
        : "+f"(d[0]), "+f"(d[1]), "+f"(d[2]), "+f"(d[3])
        : "r"(a[0]), "r"(a[1]), "r"(a[2]), "r"(a[3]), "r"(b[0]), "r"(b[1]));
}
__device__ __forceinline__ void cp16(uint32_t d, const void* s) {
    asm volatile("cp.async.cg.shared.global [%0], [%1], 16;" :: "r"(d), "l"(s));
}
__device__ __forceinline__ void cp_commit() {
    asm volatile("cp.async.commit_group;" ::: "memory");
}
__device__ __forceinline__ void cp_wait1() {
    asm volatile("cp.async.wait_group 1;" ::: "memory");
}
__device__ __forceinline__ uint32_t pk(__nv_bfloat16 a, __nv_bfloat16 b) {
    __nv_bfloat162 t = __halves2bfloat162(a, b);
    return *reinterpret_cast<uint32_t*>(&t);
}
__device__ __forceinline__ void split1(float x, __nv_bfloat16& h, __nv_bfloat16& l) {
    h = __float2bfloat16(x);
    l = __float2bfloat16(x - __bfloat162float(h));
}
// swizzled byte offset, 128-byte rows (64 bf16)
__device__ __forceinline__ uint32_t swz(uint32_t row, uint32_t kbyte) {
    return (row * 128 + kbyte) ^ ((row & 7) << 4);
}
// swizzled byte offset, 256-byte rows (128 bf16)
__device__ __forceinline__ uint32_t swz256(uint32_t row, uint32_t kbyte) {
    return (row * 256 + kbyte) ^ ((row & 7) << 4);
}

// ---------------------------------------------------------------------------
// elementwise fp32 -> bf16 hi/lo (same layout)
// ---------------------------------------------------------------------------
__global__ __launch_bounds__(256) void split_a_kernel(
    const float* __restrict__ A, __nv_bfloat16* __restrict__ Ah,
    __nv_bfloat16* __restrict__ Al, size_t n4)
{
    size_t i = (size_t)blockIdx.x * blockDim.x + threadIdx.x;
    if (i >= n4) return;
    float4 v = *(const float4*)&A[4 * i];
    __nv_bfloat16 h0, h1, h2, h3, l0, l1, l2, l3;
    split1(v.x, h0, l0); split1(v.y, h1, l1);
    split1(v.z, h2, l2); split1(v.w, h3, l3);
    uint2 hv, lv;
    hv.x = pk(h0, h1); hv.y = pk(h2, h3);
    lv.x = pk(l0, l1); lv.y = pk(l2, l3);
    *(uint2*)&Ah[4 * i] = hv;
    *(uint2*)&Al[4 * i] = lv;
}

// ---------------------------------------------------------------------------
// W [K][N] fp32 -> WhT/WlT [N][K] bf16 (tiled transpose + split)
// ---------------------------------------------------------------------------
__global__ __launch_bounds__(256) void split_wT_kernel(
    const float* __restrict__ W, __nv_bfloat16* __restrict__ WhT,
    __nv_bfloat16* __restrict__ WlT, int K, int N)
{
    __shared__ float tile[32][33];
    int nb = blockIdx.x * 32, kb = blockIdx.y * 32;
    int tx = threadIdx.x & 31, ty = threadIdx.x >> 5;   // 32 x 8
#pragma unroll
    for (int r = 0; r < 4; r++)
        tile[ty + 8 * r][tx] = W[(size_t)(kb + ty + 8 * r) * N + nb + tx];
    __syncthreads();
#pragma unroll
    for (int r = 0; r < 4; r++) {
        int n = nb + ty + 8 * r, k = kb + tx;
        float x = tile[tx][ty + 8 * r];
        __nv_bfloat16 h, l;
        split1(x, h, l);
        WhT[(size_t)n * K + k] = h;
        WlT[(size_t)n * K + k] = l;
    }
}

// ---------------------------------------------------------------------------
// V slice of qkv fp32 [tok][...] -> V^T bf16 hi/lo [b][kvh][hd][S]
// ---------------------------------------------------------------------------
__global__ __launch_bounds__(256) void vsplitT_kernel(
    const float* __restrict__ qkv,
    __nv_bfloat16* __restrict__ VtH, __nv_bfloat16* __restrict__ VtL)
{
    __shared__ float tile[32][33];
    int s0 = blockIdx.x * 32;          // seq tile
    int d0 = blockIdx.y * 32;          // hd tile
    int bk = blockIdx.z;               // b * NKV + kvh
    int b  = bk / NKV_, kvh = bk % NKV_;
    int tx = threadIdx.x & 31, ty = threadIdx.x >> 5;

    const float* src = qkv + ((size_t)b * S_) * QKVN + QSZ + KVSZ + kvh * HD_;
#pragma unroll
    for (int r = 0; r < 4; r++) {
        int s = s0 + ty + 8 * r;
        tile[ty + 8 * r][tx] = src[(size_t)s * QKVN + d0 + tx];
    }
    __syncthreads();
#pragma unroll
    for (int r = 0; r < 4; r++) {
        int d = d0 + ty + 8 * r, s = s0 + tx;
        float x = tile[tx][ty + 8 * r];
        __nv_bfloat16 h, l;
        split1(x, h, l);
        size_t o = ((size_t)bk * HD_ + d) * S_ + s;
        VtH[o] = h;
        VtL[o] = l;
    }
}

// ---------------------------------------------------------------------------
// qkv fp32 -> rope'd bf16 hi/lo (q + k heads only), float2-vectorized.
// ---------------------------------------------------------------------------
__global__ __launch_bounds__(256) void rope_split_kernel(
    const float* __restrict__ qkv,
    const float* __restrict__ cosb, const float* __restrict__ sinb,
    __nv_bfloat16* __restrict__ oh, __nv_bfloat16* __restrict__ ol)
{
    int idx = blockIdx.x * blockDim.x + threadIdx.x;   // TOK * 640
    int p   = idx % 640;
    int tok = idx / 640;
    if (tok >= TOK) return;
    int s = tok & (S_ - 1);
    size_t base = (size_t)tok * QKVN;

    int head = p >> 5;                 // 0..19
    int dd   = (p & 31) * 2;           // even d
    int off = (head < NH_) ? head * HD_ : QSZ + (head - NH_) * HD_;
    float2 c2v = *(const float2*)&cosb[s * 64 + dd];
    float2 s2v = *(const float2*)&sinb[s * 64 + dd];
    float2 x1 = *(const float2*)&qkv[base + off + dd];
    float2 x2 = *(const float2*)&qkv[base + off + dd + 64];

    float y1a = x1.x * c2v.x - x2.x * s2v.x;
    float y1b = x1.y * c2v.y - x2.y * s2v.y;
    float y2a = x2.x * c2v.x + x1.x * s2v.x;
    float y2b = x2.y * c2v.y + x1.y * s2v.y;

    __nv_bfloat16 h0, l0, h1, l1;
    split1(y1a, h0, l0); split1(y1b, h1, l1);
    *(uint32_t*)&oh[base + off + dd] = pk(h0, h1);
    *(uint32_t*)&ol[base + off + dd] = pk(l0, l1);
    split1(y2a, h0, l0); split1(y2b, h1, l1);
    *(uint32_t*)&oh[base + off + dd + 64] = pk(h0, h1);
    *(uint32_t*)&ol[base + off + dd + 64] = pk(l0, l1);
}

// ---------------------------------------------------------------------------
// bf16x3 mma.sync GEMM — EXACT R13 (cp.async 3-stage, issue AFTER compute).
// ---------------------------------------------------------------------------
#define GKC     64
#define STG_B   65536
#define SOFF_AH 0
#define SOFF_AL 16384
#define SOFF_BH 32768
#define SOFF_BL 49152
#define GEMM_SMEM (3 * STG_B)

__global__ __launch_bounds__(256, 1) void gemm3x_kernel(
    const __nv_bfloat16* __restrict__ Ah, const __nv_bfloat16* __restrict__ Al,
    const __nv_bfloat16* __restrict__ BhT, const __nv_bfloat16* __restrict__ BlT,
    const float* __restrict__ bias, float* __restrict__ C,
    int M, int N, int K)
{
    extern __shared__ char smem[];
    const uint32_t sbase = smem_u32(smem);
    const int tid = threadIdx.x;
    const int wid = tid >> 5, lane = tid & 31;
    const int m0 = blockIdx.y * 128, n0 = blockIdx.x * 128;
    const int wm = wid & 3;
    const int wn = wid >> 2;

    const int prow = tid >> 3;
    const int pks  = tid & 7;

    float acc[2][8][4];
#pragma unroll
    for (int i = 0; i < 2; i++)
#pragma unroll
        for (int j = 0; j < 8; j++)
#pragma unroll
            for (int q = 0; q < 4; q++) acc[i][j][q] = 0.f;

    const int NC = K / GKC;

#define GEMM_ISSUE(c)                                                          \
    do {                                                                       \
        if ((c) < NC) {                                                        \
            uint32_t stg = sbase + ((c) % 3) * STG_B;                          \
            int kc = (c) * GKC;                                                \
            _Pragma("unroll")                                                  \
            for (int i_ = 0; i_ < 4; i_++) {                                   \
                int row = prow + 32 * i_;                                      \
                uint32_t off = swz(row, pks * 16);                             \
                size_t ao = (size_t)(m0 + row) * K + kc + pks * 8;             \
                size_t bo = (size_t)(n0 + row) * K + kc + pks * 8;             \
                cp16(stg + SOFF_AH + off, Ah + ao);                            \
                cp16(stg + SOFF_AL + off, Al + ao);                            \
                cp16(stg + SOFF_BH + off, BhT + bo);                           \
                cp16(stg + SOFF_BL + off, BlT + bo);                           \
            }                                                                  \
        }                                                                      \
    } while (0)

    GEMM_ISSUE(0); cp_commit();
    GEMM_ISSUE(1); cp_commit();

    const int a_row = wm * 32 + (lane & 15);
    const int a_kh  = (lane >> 4) << 4;
    const int b_row = wn * 64 + ((lane >> 4) << 3) + (lane & 7);
    const int b_kh  = ((lane >> 3) & 1) << 4;

    for (int c = 0; c < NC; c++) {
        cp_wait1();
        __syncthreads();

        const uint32_t sb = sbase + (c % 3) * STG_B;
#pragma unroll
        for (int s = 0; s < 4; s++) {
            const uint32_t kbyte = 32 * s;
            uint32_t ah[2][4], al[2][4];
#pragma unroll
            for (int ti = 0; ti < 2; ti++) {
                uint32_t ra = swz(a_row + 16 * ti, kbyte + a_kh);
                ldsm_x4(sb + SOFF_AH + ra, ah[ti][0], ah[ti][1], ah[ti][2], ah[ti][3]);
                ldsm_x4(sb + SOFF_AL + ra, al[ti][0], al[ti][1], al[ti][2], al[ti][3]);
            }
#pragma unroll
            for (int pj = 0; pj < 4; pj++) {
                uint32_t rb = swz(b_row + 16 * pj, kbyte + b_kh);
                uint32_t bh[4], bl[4];
                ldsm_x4(sb + SOFF_BH + rb, bh[0], bh[1], bh[2], bh[3]);
                ldsm_x4(sb + SOFF_BL + rb, bl[0], bl[1], bl[2], bl[3]);
#pragma unroll
                for (int ti = 0; ti < 2; ti++) {
                    mma_bf16(acc[ti][2 * pj + 0], ah[ti], bh + 0);
                    mma_bf16(acc[ti][2 * pj + 1], ah[ti], bh + 2);
                    mma_bf16(acc[ti][2 * pj + 0], ah[ti], bl + 0);
                    mma_bf16(acc[ti][2 * pj + 1], ah[ti], bl + 2);
                    mma_bf16(acc[ti][2 * pj + 0], al[ti], bh + 0);
                    mma_bf16(acc[ti][2 * pj + 1], al[ti], bh + 2);
                }
            }
        }

        GEMM_ISSUE(c + 2);
        cp_commit();
    }

#pragma unroll
    for (int tj = 0; tj < 8; tj++) {
        int col = n0 + wn * 64 + tj * 8 + 2 * (lane & 3);
        float2 bb = *(const float2*)&bias[col];
#pragma unroll
        for (int ti = 0; ti < 2; ti++) {
            int row = m0 + wm * 32 + ti * 16 + (lane >> 2);
            float2 v0, v1;
            v0.x = acc[ti][tj][0] + bb.x; v0.y = acc[ti][tj][1] + bb.y;
            v1.x = acc[ti][tj][2] + bb.x; v1.y = acc[ti][tj][3] + bb.y;
            *(float2*)&C[(size_t)row * N + col] = v0;
            *(float2*)&C[(size_t)(row + 8) * N + col] = v1;
        }
    }
#undef GEMM_ISSUE
}

// ---------------------------------------------------------------------------
// Tensor-core flash attention — R13 structure with one change: ATTN_ISSUE(t+2)
// moved into the softmax shadow (after QK^T consumption of K for this tile,
// before the softmax/PV). Same safety proof: stage (t+2)%3 == (t-1)%3 whose
// readers (tile t-1's consumers) passed this iteration's barrier.
// ---------------------------------------------------------------------------
#define ASTG  65536
#define AKH   0
#define AKL   16384
#define AVH   32768
#define AVL   49152
#define ATTN2_SMEM (3 * ASTG)

__global__ __launch_bounds__(256, 1) void attn_mma_kernel(
    const __nv_bfloat16* __restrict__ qh, const __nv_bfloat16* __restrict__ ql,
    const __nv_bfloat16* __restrict__ vth, const __nv_bfloat16* __restrict__ vtl,
    __nv_bfloat16* __restrict__ outh, __nv_bfloat16* __restrict__ outl)
{
    extern __shared__ char sm[];
    const uint32_t sb = smem_u32(sm);
    const int tid = threadIdx.x;
    const int wid = tid >> 5, lane = tid & 31;
    const int q0 = blockIdx.x * 128;
    const int h  = blockIdx.y;
    const int b  = blockIdx.z;
    const int kvh = h >> 2;

    const float scale = 0.08838834764831845f;   // 1/sqrt(128)
    const size_t tok0 = (size_t)b * S_;
    const __nv_bfloat16* qbh = qh + (tok0 + q0) * QKVN + h * HD_;
    const __nv_bfloat16* qbl = ql + (tok0 + q0) * QKVN + h * HD_;
    const __nv_bfloat16* kbh = qh + tok0 * QKVN + QSZ + kvh * HD_;
    const __nv_bfloat16* kbl = ql + tok0 * QKVN + QSZ + kvh * HD_;
    const __nv_bfloat16* vbh = vth + (size_t)(b * NKV_ + kvh) * HD_ * S_;
    const __nv_bfloat16* vbl = vtl + (size_t)(b * NKV_ + kvh) * HD_ * S_;

    const int NT = S_ / 64;   // 32

    const int krow = tid >> 4, kks = tid & 15;   // K: 64 rows x 16 units (256B)
    const int vrow = tid >> 3, vks = tid & 7;    // V^T: 128 rows x 8 units (128B)

#define ATTN_ISSUE(t)                                                          \
    do {                                                                       \
        if ((t) < NT) {                                                        \
            uint32_t stg = sb + ((t) % 3) * ASTG;                              \
            size_t tb = (size_t)(t) * 64;                                      \
            _Pragma("unroll")                                                  \
            for (int i_ = 0; i_ < 4; i_++) {                                   \
                int rk = krow + 16 * i_;                                       \
                uint32_t ko = swz256(rk, kks * 16);                            \
                size_t kg = (tb + rk) * QKVN + kks * 8;                        \
                cp16(stg + AKH + ko, kbh + kg);                                \
                cp16(stg + AKL + ko, kbl + kg);                                \
                int rv = vrow + 32 * i_;                                       \
                uint32_t vo = swz(rv, vks * 16);                               \
                size_t vg = (size_t)rv * S_ + tb + vks * 8;                    \
                cp16(stg + AVH + vo, vbh + vg);                                \
                cp16(stg + AVL + vo, vbl + vg);                                \
            }                                                                  \
        }                                                                      \
    } while (0)

    // ---- prologue: Q into stage 0 region (hi at +0, lo at +32KB) ----
#pragma unroll
    for (int i = 0; i < 8; i++) {
        int u = tid + 256 * i;
        int row = u >> 4, ks = u & 15;
        uint32_t off = swz256(row, ks * 16);
        *(uint4*)(sm + off)         = *(const uint4*)&qbh[(size_t)row * QKVN + ks * 8];
        *(uint4*)(sm + 32768 + off) = *(const uint4*)&qbl[(size_t)row * QKVN + ks * 8];
    }
    __syncthreads();

    const int a_row = wid * 16 + (lane & 15);
    const int a_kh  = (lane >> 4) << 4;
    uint32_t qfh[8][4], qfl[8][4];
#pragma unroll
    for (int s = 0; s < 8; s++) {
        uint32_t ra = swz256(a_row, s * 32 + a_kh);
        ldsm_x4(sb + ra,         qfh[s][0], qfh[s][1], qfh[s][2], qfh[s][3]);
        ldsm_x4(sb + 32768 + ra, qfl[s][0], qfl[s][1], qfl[s][2], qfl[s][3]);
    }
    __syncthreads();

    ATTN_ISSUE(0); cp_commit();
    ATTN_ISSUE(1); cp_commit();

    float o[16][4];
#pragma unroll
    for (int j = 0; j < 16; j++)
#pragma unroll
        for (int q = 0; q < 4; q++) o[j][q] = 0.f;
    float m0r = -1e30f, m1r = -1e30f, l0r = 0.f, l1r = 0.f;

    const int b_rsub = ((lane >> 4) << 3) + (lane & 7);
    const int b_kh   = ((lane >> 3) & 1) << 4;

    for (int t = 0; t < NT; t++) {
        cp_wait1();
        __syncthreads();

        const uint32_t kvb = sb + (t % 3) * ASTG;

        // ---- QK^T (Q from registers) ----
        float sc[8][4];
#pragma unroll
        for (int j = 0; j < 8; j++)
#pragma unroll
            for (int q = 0; q < 4; q++) sc[j][q] = 0.f;

#pragma unroll
        for (int s = 0; s < 8; s++) {
#pragma unroll
            for (int nb = 0; nb < 4; nb++) {
                uint32_t rb = swz256(nb * 16 + b_rsub, s * 32 + b_kh);
                uint32_t bh[4], bl[4];
                ldsm_x4(kvb + AKH + rb, bh[0], bh[1], bh[2], bh[3]);
                ldsm_x4(kvb + AKL + rb, bl[0], bl[1], bl[2], bl[3]);
                mma_bf16(sc[2 * nb + 0], qfh[s], bh + 0);
                mma_bf16(sc[2 * nb + 1], qfh[s], bh + 2);
                mma_bf16(sc[2 * nb + 0], qfh[s], bl + 0);
                mma_bf16(sc[2 * nb + 1], qfh[s], bl + 2);
                mma_bf16(sc[2 * nb + 0], qfl[s], bh + 0);
                mma_bf16(sc[2 * nb + 1], qfl[s], bh + 2);
            }
        }

        // ---- issue tile t+2 in the softmax shadow (LSU drains under FMA) ----
        ATTN_ISSUE(t + 2);
        cp_commit();

        // ---- online softmax ----
        float mx0 = -1e30f, mx1 = -1e30f;
#pragma unroll
        for (int j = 0; j < 8; j++) {
            sc[j][0] *= scale; sc[j][1] *= scale;
            sc[j][2] *= scale; sc[j][3] *= scale;
            mx0 = fmaxf(mx0, fmaxf(sc[j][0], sc[j][1]));
            mx1 = fmaxf(mx1, fmaxf(sc[j][2], sc[j][3]));
        }
        mx0 = fmaxf(mx0, __shfl_xor_sync(0xffffffffu, mx0, 1));
        mx0 = fmaxf(mx0, __shfl_xor_sync(0xffffffffu, mx0, 2));
        mx1 = fmaxf(mx1, __shfl_xor_sync(0xffffffffu, mx1, 1));
        mx1 = fmaxf(mx1, __shfl_xor_sync(0xffffffffu, mx1, 2));
        float mn0 = fmaxf(m0r, mx0), mn1 = fmaxf(m1r, mx1);
        float al0 = __expf(m0r - mn0), al1 = __expf(m1r - mn1);

        float ls0 = 0.f, ls1 = 0.f;
        uint32_t pa[4][4], pal[4][4];
#pragma unroll
        for (int j = 0; j < 8; j++) {
            float p00 = __expf(sc[j][0] - mn0);
            float p01 = __expf(sc[j][1] - mn0);
            float p10 = __expf(sc[j][2] - mn1);
            float p11 = __expf(sc[j][3] - mn1);
            ls0 += p00 + p01; ls1 += p10 + p11;
            __nv_bfloat16 h00, l00, h01, l01, h10, l10, h11, l11;
            split1(p00, h00, l00); split1(p01, h01, l01);
            split1(p10, h10, l10); split1(p11, h11, l11);
            int kk = j >> 1, hf = (j & 1) << 1;
            pa[kk][hf + 0] = pk(h00, h01);
            pa[kk][hf + 1] = pk(h10, h11);
            pal[kk][hf + 0] = pk(l00, l01);
            pal[kk][hf + 1] = pk(l10, l11);
        }
        ls0 += __shfl_xor_sync(0xffffffffu, ls0, 1);
        ls0 += __shfl_xor_sync(0xffffffffu, ls0, 2);
        ls1 += __shfl_xor_sync(0xffffffffu, ls1, 1);
        ls1 += __shfl_xor_sync(0xffffffffu, ls1, 2);
        l0r = l0r * al0 + ls0;
        l1r = l1r * al1 + ls1;
        m0r = mn0; m1r = mn1;

        // alpha-skip: multiply-by-1.0f is bitwise identity -> skipping is
        // numerically identical.
        if (!__all_sync(0xffffffffu, (al0 == 1.f) && (al1 == 1.f))) {
#pragma unroll
            for (int j = 0; j < 16; j++) {
                o[j][0] *= al0; o[j][1] *= al0;
                o[j][2] *= al1; o[j][3] *= al1;
            }
        }

        // ---- PV ----
#pragma unroll
        for (int kk = 0; kk < 4; kk++) {
#pragma unroll
            for (int nb = 0; nb < 8; nb++) {
                uint32_t rv = swz(nb * 16 + b_rsub, kk * 32 + b_kh);
                uint32_t vh[4], vl[4];
                ldsm_x4(kvb + AVH + rv, vh[0], vh[1], vh[2], vh[3]);
                ldsm_x4(kvb + AVL + rv, vl[0], vl[1], vl[2], vl[3]);
                mma_bf16(o[2 * nb + 0], pa[kk], vh + 0);
                mma_bf16(o[2 * nb + 1], pa[kk], vh + 2);
                mma_bf16(o[2 * nb + 0], pal[kk], vh + 0);
                mma_bf16(o[2 * nb + 1], pal[kk], vh + 2);
                mma_bf16(o[2 * nb + 0], pa[kk], vl + 0);
                mma_bf16(o[2 * nb + 1], pa[kk], vl + 2);
            }
        }
    }

    // ---- epilogue: write bf16 hi/lo ----
    float inv0 = 1.f / l0r, inv1 = 1.f / l1r;
    int r0 = lane >> 2, c2 = 2 * (lane & 3);
    size_t row0 = (size_t)b * S_ + q0 + wid * 16 + r0;
#pragma unroll
    for (int j = 0; j < 16; j++) {
        int col = h * HD_ + 8 * j + c2;
        float f0 = o[j][0] * inv0, f1 = o[j][1] * inv0;
        float f2 = o[j][2] * inv1, f3 = o[j][3] * inv1;
        __nv_bfloat16 h0, l0, h1, l1, h2, l2, h3, l3;
        split1(f0, h0, l0); split1(f1, h1, l1);
        split1(f2, h2, l2); split1(f3, h3, l3);
        *(uint32_t*)&outh[row0 * HID_ + col] = pk(h0, h1);
        *(uint32_t*)&outl[row0 * HID_ + col] = pk(l0, l1);
        *(uint32_t*)&outh[(row0 + 8) * HID_ + col] = pk(h2, h3);
        *(uint32_t*)&outl[(row0 + 8) * HID_ + col] = pk(l2, l3);
    }
#undef ATTN_ISSUE
}

// ---------------------------------------------------------------------------
// kernel_launch
// ---------------------------------------------------------------------------
extern "C" void kernel_launch(void* const* d_in, const int* in_sizes, int n_in,
                              void* d_out, int out_size)
{
    const float *hidden = nullptr, *cosb = nullptr, *sinb = nullptr;
    const float *wqkv = nullptr, *bqkv = nullptr, *wo = nullptr, *bo = nullptr;
    for (int i = 0; i < n_in; i++) {
        long sz = in_sizes[i];
        const float* p = (const float*)d_in[i];
        if (sz == (long)TOK * HID_)            hidden = p;
        else if (sz == (long)S_ * 64) {
            if (!cosb) cosb = p; else sinb = p;
        }
        else if (sz == (long)HID_ * QKVN)      wqkv = p;
        else if (sz == (long)QKVN)             bqkv = p;
        else if (sz == (long)HID_ * HID_)      wo = p;
        else if (sz == (long)HID_)             bo = p;
    }
    float* out = (float*)d_out;

    float* qkv;
    __nv_bfloat16 *hid_h, *hid_l, *attn_h, *attn_l;
    __nv_bfloat16 *wqkv_h, *wqkv_l, *wo_h, *wo_l, *qkvb_h, *qkvb_l;
    __nv_bfloat16 *vt_h, *vt_l;
    cudaGetSymbolAddress((void**)&qkv, g_qkv);
    cudaGetSymbolAddress((void**)&hid_h, g_hid_h);
    cudaGetSymbolAddress((void**)&hid_l, g_hid_l);
    cudaGetSymbolAddress((void**)&attn_h, g_attn_h);
    cudaGetSymbolAddress((void**)&attn_l, g_attn_l);
    cudaGetSymbolAddress((void**)&wqkv_h, g_wqkv_h);
    cudaGetSymbolAddress((void**)&wqkv_l, g_wqkv_l);
    cudaGetSymbolAddress((void**)&wo_h, g_wo_h);
    cudaGetSymbolAddress((void**)&wo_l, g_wo_l);
    cudaGetSymbolAddress((void**)&qkvb_h, g_qkvb_h);
    cudaGetSymbolAddress((void**)&qkvb_l, g_qkvb_l);
    cudaGetSymbolAddress((void**)&vt_h, g_vt_h);
    cudaGetSymbolAddress((void**)&vt_l, g_vt_l);

    cudaFuncSetAttribute(gemm3x_kernel,
                         cudaFuncAttributeMaxDynamicSharedMemorySize, GEMM_SMEM);
    cudaFuncSetAttribute(attn_mma_kernel,
                         cudaFuncAttributeMaxDynamicSharedMemorySize, ATTN2_SMEM);

    // 0) weight + hidden pre-split
    {
        dim3 g1(QKVN / 32, HID_ / 32);
        split_wT_kernel<<<g1, 256>>>(wqkv, wqkv_h, wqkv_l, HID_, QKVN);
        dim3 g2(HID_ / 32, HID_ / 32);
        split_wT_kernel<<<g2, 256>>>(wo, wo_h, wo_l, HID_, HID_);
        size_t n4 = (size_t)TOK * HID_ / 4;
        split_a_kernel<<<(unsigned)((n4 + 255) / 256), 256>>>(hidden, hid_h, hid_l, n4);
    }
    // 1) QKV projection (tile 128x128)
    {
        dim3 grid(QKVN / 128, TOK / 128);  // (24, 64)
        gemm3x_kernel<<<grid, 256, GEMM_SMEM>>>(hid_h, hid_l, wqkv_h, wqkv_l,
                                                bqkv, qkv, TOK, QKVN, HID_);
    }
    // 2) RoPE + split (q,k) and V transpose + split
    {
        int total = TOK * 640;
        rope_split_kernel<<<total / 256, 256>>>(qkv, cosb, sinb, qkvb_h, qkvb_l);
        dim3 gv(S_ / 32, HD_ / 32, B_ * NKV_);
        vsplitT_kernel<<<gv, 256>>>(qkv, vt_h, vt_l);
    }
    // 3) Attention (cp.async 3-stage, bf16 hi/lo out)
    {
        dim3 grid(S_ / 128, NH_, B_);  // (16, 16, 4)
        attn_mma_kernel<<<grid, 256, ATTN2_SMEM>>>(qkvb_h, qkvb_l, vt_h, vt_l,
                                                   attn_h, attn_l);
    }
    // 4) Output projection (tile 128x128)
    {
        dim3 grid(HID_ / 128, TOK / 128);  // (16, 64)
        gemm3x_kernel<<<grid, 256, GEMM_SMEM>>>(attn_h, attn_l, wo_h, wo_l,
                                                bo, out, TOK, HID_, HID_);
    }
}

// round 16
// speedup vs baseline: 1.0199x; 1.0199x over previous
#include <cuda_runtime.h>
#include <cuda_bf16.h>
#include <cstdint>
#include <math.h>

// ---------------------------------------------------------------------------
// Problem constants: B=4, S=2048, HID=2048, NH=16, NKV=4, HD=128.
// ---------------------------------------------------------------------------
#define B_    4
#define S_    2048
#define HID_  2048
#define NH_   16
#define NKV_  4
#define HD_   128
#define QSZ   (NH_ * HD_)          // 2048
#define KVSZ  (NKV_ * HD_)         // 512
#define QKVN  (QSZ + 2 * KVSZ)     // 3072
#define TOK   (B_ * S_)            // 8192

// Scratch (device globals; no allocs allowed)
__device__ __align__(16) __nv_bfloat16  g_hid_h[(size_t)TOK * HID_];
__device__ __align__(16) __nv_bfloat16  g_hid_l[(size_t)TOK * HID_];
__device__ __align__(16) __nv_bfloat16  g_attn_h[(size_t)TOK * HID_];
__device__ __align__(16) __nv_bfloat16  g_attn_l[(size_t)TOK * HID_];
__device__ __align__(16) __nv_bfloat16  g_wqkv_h[(size_t)QKVN * HID_];  // [N][K]
__device__ __align__(16) __nv_bfloat16  g_wqkv_l[(size_t)QKVN * HID_];
__device__ __align__(16) __nv_bfloat16  g_wo_h[(size_t)HID_ * HID_];    // [N][K]
__device__ __align__(16) __nv_bfloat16  g_wo_l[(size_t)HID_ * HID_];
__device__ __align__(16) __nv_bfloat16  g_qkvb_h[(size_t)TOK * QKVN];   // rope'd q,k
__device__ __align__(16) __nv_bfloat16  g_qkvb_l[(size_t)TOK * QKVN];
// V^T pre-transposed: [b][kvh][hd][S]
__device__ __align__(16) __nv_bfloat16  g_vt_h[(size_t)B_ * NKV_ * HD_ * S_];
__device__ __align__(16) __nv_bfloat16  g_vt_l[(size_t)B_ * NKV_ * HD_ * S_];

// ---------------------------------------------------------------------------
// Helpers
// ---------------------------------------------------------------------------
__device__ __forceinline__ uint32_t smem_u32(const void* p) {
    uint32_t a;
    asm("{ .reg .u64 t; cvta.to.shared.u64 t, %1; cvt.u32.u64 %0, t; }"
        : "=r"(a) : "l"(p));
    return a;
}
__device__ __forceinline__ void ldsm_x4(uint32_t addr, uint32_t& r0, uint32_t& r1,
                                        uint32_t& r2, uint32_t& r3) {
    asm volatile("ldmatrix.sync.aligned.m8n8.x4.shared.b16 {%0,%1,%2,%3}, [%4];"
                 : "=r"(r0), "=r"(r1), "=r"(r2), "=r"(r3) : "r"(addr));
}
__device__ __forceinline__ void mma_bf16(float* d, const uint32_t* a,
                                         const uint32_t* b) {
    asm volatile(
        "mma.sync.aligned.m16n8k16.row.col.f32.bf16.bf16.f32 "
        "{%0,%1,%2,%3}, {%4,%5,%6,%7}, {%8,%9}, {%0,%1,%2,%3};"
        : "+f"(d[0]), "+f"(d[1]), "+f"(d[2]), "+f"(d[3])
        : "r"(a[0]), "r"(a[1]), "r"(a[2]), "r"(a[3]), "r"(b[0]), "r"(b[1]));
}
__device__ __forceinline__ void cp16(uint32_t d, const void* s) {
    asm volatile("cp.async.cg.shared.global [%0], [%1], 16;" :: "r"(d), "l"(s));
}
__device__ __forceinline__ void cp_commit() {
    asm volatile("cp.async.commit_group;" ::: "memory");
}
__device__ __forceinline__ void cp_wait1() {
    asm volatile("cp.async.wait_group 1;" ::: "memory");
}
__device__ __forceinline__ uint32_t pk(__nv_bfloat16 a, __nv_bfloat16 b) {
    __nv_bfloat162 t = __halves2bfloat162(a, b);
    return *reinterpret_cast<uint32_t*>(&t);
}
__device__ __forceinline__ void split1(float x, __nv_bfloat16& h, __nv_bfloat16& l) {
    h = __float2bfloat16(x);
    l = __float2bfloat16(x - __bfloat162float(h));
}
// swizzled byte offset, 128-byte rows (64 bf16)
__device__ __forceinline__ uint32_t swz(uint32_t row, uint32_t kbyte) {
    return (row * 128 + kbyte) ^ ((row & 7) << 4);
}
// swizzled byte offset, 256-byte rows (128 bf16)
__device__ __forceinline__ uint32_t swz256(uint32_t row, uint32_t kbyte) {
    return (row * 256 + kbyte) ^ ((row & 7) << 4);
}

// ---------------------------------------------------------------------------
// elementwise fp32 -> bf16 hi/lo (same layout)
// ---------------------------------------------------------------------------
__global__ __launch_bounds__(256) void split_a_kernel(
    const float* __restrict__ A, __nv_bfloat16* __restrict__ Ah,
    __nv_bfloat16* __restrict__ Al, size_t n4)
{
    size_t i = (size_t)blockIdx.x * blockDim.x + threadIdx.x;
    if (i >= n4) return;
    float4 v = *(const float4*)&A[4 * i];
    __nv_bfloat16 h0, h1, h2, h3, l0, l1, l2, l3;
    split1(v.x, h0, l0); split1(v.y, h1, l1);
    split1(v.z, h2, l2); split1(v.w, h3, l3);
    uint2 hv, lv;
    hv.x = pk(h0, h1); hv.y = pk(h2, h3);
    lv.x = pk(l0, l1); lv.y = pk(l2, l3);
    *(uint2*)&Ah[4 * i] = hv;
    *(uint2*)&Al[4 * i] = lv;
}

// ---------------------------------------------------------------------------
// W [K][N] fp32 -> WhT/WlT [N][K] bf16 (tiled transpose + split)
// ---------------------------------------------------------------------------
__global__ __launch_bounds__(256) void split_wT_kernel(
    const float* __restrict__ W, __nv_bfloat16* __restrict__ WhT,
    __nv_bfloat16* __restrict__ WlT, int K, int N)
{
    __shared__ float tile[32][33];
    int nb = blockIdx.x * 32, kb = blockIdx.y * 32;
    int tx = threadIdx.x & 31, ty = threadIdx.x >> 5;   // 32 x 8
#pragma unroll
    for (int r = 0; r < 4; r++)
        tile[ty + 8 * r][tx] = W[(size_t)(kb + ty + 8 * r) * N + nb + tx];
    __syncthreads();
#pragma unroll
    for (int r = 0; r < 4; r++) {
        int n = nb + ty + 8 * r, k = kb + tx;
        float x = tile[tx][ty + 8 * r];
        __nv_bfloat16 h, l;
        split1(x, h, l);
        WhT[(size_t)n * K + k] = h;
        WlT[(size_t)n * K + k] = l;
    }
}

// ---------------------------------------------------------------------------
// Shared GEMM macros (R13 mainloop)
// ---------------------------------------------------------------------------
#define GKC     64
#define STG_B   65536
#define SOFF_AH 0
#define SOFF_AL 16384
#define SOFF_BH 32768
#define SOFF_BL 49152
#define GEMM_SMEM (3 * STG_B)

#define GEMM_PROLOGUE()                                                        \
    extern __shared__ char smem[];                                             \
    const uint32_t sbase = smem_u32(smem);                                     \
    const int tid = threadIdx.x;                                               \
    const int wid = tid >> 5, lane = tid & 31;                                 \
    const int m0 = blockIdx.y * 128, n0 = blockIdx.x * 128;                    \
    const int wm = wid & 3;                                                    \
    const int wn = wid >> 2;                                                   \
    const int prow = tid >> 3;                                                 \
    const int pks  = tid & 7;                                                  \
    float acc[2][8][4];                                                        \
    _Pragma("unroll")                                                          \
    for (int i = 0; i < 2; i++)                                                \
        _Pragma("unroll")                                                      \
        for (int j = 0; j < 8; j++)                                            \
            _Pragma("unroll")                                                  \
            for (int q = 0; q < 4; q++) acc[i][j][q] = 0.f;                    \
    const int NC = K / GKC;

#define GEMM_ISSUE(c)                                                          \
    do {                                                                       \
        if ((c) < NC) {                                                        \
            uint32_t stg = sbase + ((c) % 3) * STG_B;                          \
            int kc = (c) * GKC;                                                \
            _Pragma("unroll")                                                  \
            for (int i_ = 0; i_ < 4; i_++) {                                   \
                int row = prow + 32 * i_;                                      \
                uint32_t off = swz(row, pks * 16);                             \
                size_t ao = (size_t)(m0 + row) * K + kc + pks * 8;             \
                size_t bo = (size_t)(n0 + row) * K + kc + pks * 8;             \
                cp16(stg + SOFF_AH + off, Ah + ao);                            \
                cp16(stg + SOFF_AL + off, Al + ao);                            \
                cp16(stg + SOFF_BH + off, BhT + bo);                           \
                cp16(stg + SOFF_BL + off, BlT + bo);                           \
            }                                                                  \
        }                                                                      \
    } while (0)

#define GEMM_MAINLOOP()                                                        \
    GEMM_ISSUE(0); cp_commit();                                                \
    GEMM_ISSUE(1); cp_commit();                                                \
    const int a_row = wm * 32 + (lane & 15);                                   \
    const int a_kh  = (lane >> 4) << 4;                                        \
    const int b_row = wn * 64 + ((lane >> 4) << 3) + (lane & 7);               \
    const int b_kh  = ((lane >> 3) & 1) << 4;                                  \
    for (int c = 0; c < NC; c++) {                                             \
        cp_wait1();                                                            \
        __syncthreads();                                                       \
        const uint32_t sb = sbase + (c % 3) * STG_B;                           \
        _Pragma("unroll")                                                      \
        for (int s = 0; s < 4; s++) {                                          \
            const uint32_t kbyte = 32 * s;                                     \
            uint32_t ah[2][4], al[2][4];                                       \
            _Pragma("unroll")                                                  \
            for (int ti = 0; ti < 2; ti++) {                                   \
                uint32_t ra = swz(a_row + 16 * ti, kbyte + a_kh);              \
                ldsm_x4(sb + SOFF_AH + ra, ah[ti][0], ah[ti][1], ah[ti][2], ah[ti][3]); \
                ldsm_x4(sb + SOFF_AL + ra, al[ti][0], al[ti][1], al[ti][2], al[ti][3]); \
            }                                                                  \
            _Pragma("unroll")                                                  \
            for (int pj = 0; pj < 4; pj++) {                                   \
                uint32_t rb = swz(b_row + 16 * pj, kbyte + b_kh);              \
                uint32_t bh[4], bl[4];                                         \
                ldsm_x4(sb + SOFF_BH + rb, bh[0], bh[1], bh[2], bh[3]);        \
                ldsm_x4(sb + SOFF_BL + rb, bl[0], bl[1], bl[2], bl[3]);        \
                _Pragma("unroll")                                              \
                for (int ti = 0; ti < 2; ti++) {                               \
                    mma_bf16(acc[ti][2 * pj + 0], ah[ti], bh + 0);             \
                    mma_bf16(acc[ti][2 * pj + 1], ah[ti], bh + 2);             \
                    mma_bf16(acc[ti][2 * pj + 0], ah[ti], bl + 0);             \
                    mma_bf16(acc[ti][2 * pj + 1], ah[ti], bl + 2);             \
                    mma_bf16(acc[ti][2 * pj + 0], al[ti], bh + 0);             \
                    mma_bf16(acc[ti][2 * pj + 1], al[ti], bh + 2);             \
                }                                                              \
            }                                                                  \
        }                                                                      \
        GEMM_ISSUE(c + 2);                                                     \
        cp_commit();                                                           \
    }

// ---------------------------------------------------------------------------
// bf16x3 mma.sync GEMM — EXACT R13 (plain fp32 epilogue; out-projection).
// ---------------------------------------------------------------------------
__global__ __launch_bounds__(256, 1) void gemm3x_kernel(
    const __nv_bfloat16* __restrict__ Ah, const __nv_bfloat16* __restrict__ Al,
    const __nv_bfloat16* __restrict__ BhT, const __nv_bfloat16* __restrict__ BlT,
    const float* __restrict__ bias, float* __restrict__ C,
    int M, int N, int K)
{
    GEMM_PROLOGUE();
    GEMM_MAINLOOP();

#pragma unroll
    for (int tj = 0; tj < 8; tj++) {
        int col = n0 + wn * 64 + tj * 8 + 2 * (lane & 3);
        float2 bb = *(const float2*)&bias[col];
#pragma unroll
        for (int ti = 0; ti < 2; ti++) {
            int row = m0 + wm * 32 + ti * 16 + (lane >> 2);
            float2 v0, v1;
            v0.x = acc[ti][tj][0] + bb.x; v0.y = acc[ti][tj][1] + bb.y;
            v1.x = acc[ti][tj][2] + bb.x; v1.y = acc[ti][tj][3] + bb.y;
            *(float2*)&C[(size_t)row * N + col] = v0;
            *(float2*)&C[(size_t)(row + 8) * N + col] = v1;
        }
    }
}

// ---------------------------------------------------------------------------
// QKV GEMM with fused RoPE/split/V^T epilogue (separately compiled — no mode
// branch; R14's proven epilogue on R13's mainloop).
// ---------------------------------------------------------------------------
__global__ __launch_bounds__(256, 1) void gemm_qkv_fused_kernel(
    const __nv_bfloat16* __restrict__ Ah, const __nv_bfloat16* __restrict__ Al,
    const __nv_bfloat16* __restrict__ BhT, const __nv_bfloat16* __restrict__ BlT,
    const float* __restrict__ bias,
    const float* __restrict__ cosb, const float* __restrict__ sinb,
    __nv_bfloat16* __restrict__ oh, __nv_bfloat16* __restrict__ ol,
    __nv_bfloat16* __restrict__ vth, __nv_bfloat16* __restrict__ vtl,
    int M, int N, int K)
{
    GEMM_PROLOGUE();
    GEMM_MAINLOOP();

    // ---- fused QKV epilogue (R14 exact) ----
    __syncthreads();   // all warps done with pipeline smem
    float* Cs = (float*)smem;   // [128][129] fp32, 66KB

#pragma unroll
    for (int tj = 0; tj < 8; tj++) {
        int col = wn * 64 + tj * 8 + 2 * (lane & 3);
        float2 bb = *(const float2*)&bias[n0 + col];
#pragma unroll
        for (int ti = 0; ti < 2; ti++) {
            int row = wm * 32 + ti * 16 + (lane >> 2);
            Cs[row * 129 + col]     = acc[ti][tj][0] + bb.x;
            Cs[row * 129 + col + 1] = acc[ti][tj][1] + bb.y;
            Cs[(row + 8) * 129 + col]     = acc[ti][tj][2] + bb.x;
            Cs[(row + 8) * 129 + col + 1] = acc[ti][tj][3] + bb.y;
        }
    }
    __syncthreads();

    if (n0 < QSZ + KVSZ) {
        // q/k tile: RoPE + split
        const int dcol = (tid & 31) * 2;       // 0..62
        const int rbase = tid >> 5;            // 0..7
#pragma unroll
        for (int it = 0; it < 16; it++) {
            int r = it * 8 + rbase;
            int tok = m0 + r;
            int s = tok & (S_ - 1);
            float x1a = Cs[r * 129 + dcol];
            float x1b = Cs[r * 129 + dcol + 1];
            float x2a = Cs[r * 129 + dcol + 64];
            float x2b = Cs[r * 129 + dcol + 65];
            float2 c2v = *(const float2*)&cosb[s * 64 + dcol];
            float2 s2v = *(const float2*)&sinb[s * 64 + dcol];
            float y1a = x1a * c2v.x - x2a * s2v.x;
            float y1b = x1b * c2v.y - x2b * s2v.y;
            float y2a = x2a * c2v.x + x1a * s2v.x;
            float y2b = x2b * c2v.y + x1b * s2v.y;
            size_t base = (size_t)tok * QKVN + n0 + dcol;
            __nv_bfloat16 h0, l0, h1, l1;
            split1(y1a, h0, l0); split1(y1b, h1, l1);
            *(uint32_t*)&oh[base] = pk(h0, h1);
            *(uint32_t*)&ol[base] = pk(l0, l1);
            split1(y2a, h0, l0); split1(y2b, h1, l1);
            *(uint32_t*)&oh[base + 64] = pk(h0, h1);
            *(uint32_t*)&ol[base + 64] = pk(l0, l1);
        }
    } else {
        // v tile: transpose + split
        int kvh = (n0 - QSZ - KVSZ) >> 7;      // 0..3
        int bb_ = m0 >> 11;                     // batch index (m0 / S_)
        int s_base = m0 & (S_ - 1);
        size_t vbase = ((size_t)(bb_ * NKV_ + kvh)) * HD_ * S_;
        const int sp = (tid & 63) * 2;          // s pair base 0..126
        const int dbase = tid >> 6;             // 0..3
#pragma unroll
        for (int it = 0; it < 32; it++) {
            int dv = dbase + 4 * it;            // 0..127
            float v0 = Cs[sp * 129 + dv];
            float v1 = Cs[(sp + 1) * 129 + dv];
            __nv_bfloat16 h0, l0, h1, l1;
            split1(v0, h0, l0); split1(v1, h1, l1);
            size_t o = vbase + (size_t)dv * S_ + s_base + sp;
            *(uint32_t*)&vth[o] = pk(h0, h1);
            *(uint32_t*)&vtl[o] = pk(l0, l1);
        }
    }
}

// ---------------------------------------------------------------------------
// Tensor-core flash attention — EXACT R13 (cp.async 3-stage, Q in registers,
// issue AFTER PV, alpha-skip, bf16 hi/lo epilogue).
// ---------------------------------------------------------------------------
#define ASTG  65536
#define AKH   0
#define AKL   16384
#define AVH   32768
#define AVL   49152
#define ATTN2_SMEM (3 * ASTG)

__global__ __launch_bounds__(256, 1) void attn_mma_kernel(
    const __nv_bfloat16* __restrict__ qh, const __nv_bfloat16* __restrict__ ql,
    const __nv_bfloat16* __restrict__ vth, const __nv_bfloat16* __restrict__ vtl,
    __nv_bfloat16* __restrict__ outh, __nv_bfloat16* __restrict__ outl)
{
    extern __shared__ char sm[];
    const uint32_t sb = smem_u32(sm);
    const int tid = threadIdx.x;
    const int wid = tid >> 5, lane = tid & 31;
    const int q0 = blockIdx.x * 128;
    const int h  = blockIdx.y;
    const int b  = blockIdx.z;
    const int kvh = h >> 2;

    const float scale = 0.08838834764831845f;   // 1/sqrt(128)
    const size_t tok0 = (size_t)b * S_;
    const __nv_bfloat16* qbh = qh + (tok0 + q0) * QKVN + h * HD_;
    const __nv_bfloat16* qbl = ql + (tok0 + q0) * QKVN + h * HD_;
    const __nv_bfloat16* kbh = qh + tok0 * QKVN + QSZ + kvh * HD_;
    const __nv_bfloat16* kbl = ql + tok0 * QKVN + QSZ + kvh * HD_;
    const __nv_bfloat16* vbh = vth + (size_t)(b * NKV_ + kvh) * HD_ * S_;
    const __nv_bfloat16* vbl = vtl + (size_t)(b * NKV_ + kvh) * HD_ * S_;

    const int NT = S_ / 64;   // 32

    const int krow = tid >> 4, kks = tid & 15;   // K: 64 rows x 16 units (256B)
    const int vrow = tid >> 3, vks = tid & 7;    // V^T: 128 rows x 8 units (128B)

#define ATTN_ISSUE(t)                                                          \
    do {                                                                       \
        if ((t) < NT) {                                                        \
            uint32_t stg = sb + ((t) % 3) * ASTG;                              \
            size_t tb = (size_t)(t) * 64;                                      \
            _Pragma("unroll")                                                  \
            for (int i_ = 0; i_ < 4; i_++) {                                   \
                int rk = krow + 16 * i_;                                       \
                uint32_t ko = swz256(rk, kks * 16);                            \
                size_t kg = (tb + rk) * QKVN + kks * 8;                        \
                cp16(stg + AKH + ko, kbh + kg);                                \
                cp16(stg + AKL + ko, kbl + kg);                                \
                int rv = vrow + 32 * i_;                                       \
                uint32_t vo = swz(rv, vks * 16);                               \
                size_t vg = (size_t)rv * S_ + tb + vks * 8;                    \
                cp16(stg + AVH + vo, vbh + vg);                                \
                cp16(stg + AVL + vo, vbl + vg);                                \
            }                                                                  \
        }                                                                      \
    } while (0)

    // ---- prologue: Q into stage 0 region (hi at +0, lo at +32KB) ----
#pragma unroll
    for (int i = 0; i < 8; i++) {
        int u = tid + 256 * i;
        int row = u >> 4, ks = u & 15;
        uint32_t off = swz256(row, ks * 16);
        *(uint4*)(sm + off)         = *(const uint4*)&qbh[(size_t)row * QKVN + ks * 8];
        *(uint4*)(sm + 32768 + off) = *(const uint4*)&qbl[(size_t)row * QKVN + ks * 8];
    }
    __syncthreads();

    const int a_row = wid * 16 + (lane & 15);
    const int a_kh  = (lane >> 4) << 4;
    uint32_t qfh[8][4], qfl[8][4];
#pragma unroll
    for (int s = 0; s < 8; s++) {
        uint32_t ra = swz256(a_row, s * 32 + a_kh);
        ldsm_x4(sb + ra,         qfh[s][0], qfh[s][1], qfh[s][2], qfh[s][3]);
        ldsm_x4(sb + 32768 + ra, qfl[s][0], qfl[s][1], qfl[s][2], qfl[s][3]);
    }
    __syncthreads();

    ATTN_ISSUE(0); cp_commit();
    ATTN_ISSUE(1); cp_commit();

    float o[16][4];
#pragma unroll
    for (int j = 0; j < 16; j++)
#pragma unroll
        for (int q = 0; q < 4; q++) o[j][q] = 0.f;
    float m0r = -1e30f, m1r = -1e30f, l0r = 0.f, l1r = 0.f;

    const int b_rsub = ((lane >> 4) << 3) + (lane & 7);
    const int b_kh   = ((lane >> 3) & 1) << 4;

    for (int t = 0; t < NT; t++) {
        cp_wait1();
        __syncthreads();

        const uint32_t kvb = sb + (t % 3) * ASTG;

        // ---- QK^T (Q from registers) ----
        float sc[8][4];
#pragma unroll
        for (int j = 0; j < 8; j++)
#pragma unroll
            for (int q = 0; q < 4; q++) sc[j][q] = 0.f;

#pragma unroll
        for (int s = 0; s < 8; s++) {
#pragma unroll
            for (int nb = 0; nb < 4; nb++) {
                uint32_t rb = swz256(nb * 16 + b_rsub, s * 32 + b_kh);
                uint32_t bh[4], bl[4];
                ldsm_x4(kvb + AKH + rb, bh[0], bh[1], bh[2], bh[3]);
                ldsm_x4(kvb + AKL + rb, bl[0], bl[1], bl[2], bl[3]);
                mma_bf16(sc[2 * nb + 0], qfh[s], bh + 0);
                mma_bf16(sc[2 * nb + 1], qfh[s], bh + 2);
                mma_bf16(sc[2 * nb + 0], qfh[s], bl + 0);
                mma_bf16(sc[2 * nb + 1], qfh[s], bl + 2);
                mma_bf16(sc[2 * nb + 0], qfl[s], bh + 0);
                mma_bf16(sc[2 * nb + 1], qfl[s], bh + 2);
            }
        }

        // ---- online softmax ----
        float mx0 = -1e30f, mx1 = -1e30f;
#pragma unroll
        for (int j = 0; j < 8; j++) {
            sc[j][0] *= scale; sc[j][1] *= scale;
            sc[j][2] *= scale; sc[j][3] *= scale;
            mx0 = fmaxf(mx0, fmaxf(sc[j][0], sc[j][1]));
            mx1 = fmaxf(mx1, fmaxf(sc[j][2], sc[j][3]));
        }
        mx0 = fmaxf(mx0, __shfl_xor_sync(0xffffffffu, mx0, 1));
        mx0 = fmaxf(mx0, __shfl_xor_sync(0xffffffffu, mx0, 2));
        mx1 = fmaxf(mx1, __shfl_xor_sync(0xffffffffu, mx1, 1));
        mx1 = fmaxf(mx1, __shfl_xor_sync(0xffffffffu, mx1, 2));
        float mn0 = fmaxf(m0r, mx0), mn1 = fmaxf(m1r, mx1);
        float al0 = __expf(m0r - mn0), al1 = __expf(m1r - mn1);

        float ls0 = 0.f, ls1 = 0.f;
        uint32_t pa[4][4], pal[4][4];
#pragma unroll
        for (int j = 0; j < 8; j++) {
            float p00 = __expf(sc[j][0] - mn0);
            float p01 = __expf(sc[j][1] - mn0);
            float p10 = __expf(sc[j][2] - mn1);
            float p11 = __expf(sc[j][3] - mn1);
            ls0 += p00 + p01; ls1 += p10 + p11;
            __nv_bfloat16 h00, l00, h01, l01, h10, l10, h11, l11;
            split1(p00, h00, l00); split1(p01, h01, l01);
            split1(p10, h10, l10); split1(p11, h11, l11);
            int kk = j >> 1, hf = (j & 1) << 1;
            pa[kk][hf + 0] = pk(h00, h01);
            pa[kk][hf + 1] = pk(h10, h11);
            pal[kk][hf + 0] = pk(l00, l01);
            pal[kk][hf + 1] = pk(l10, l11);
        }
        ls0 += __shfl_xor_sync(0xffffffffu, ls0, 1);
        ls0 += __shfl_xor_sync(0xffffffffu, ls0, 2);
        ls1 += __shfl_xor_sync(0xffffffffu, ls1, 1);
        ls1 += __shfl_xor_sync(0xffffffffu, ls1, 2);
        l0r = l0r * al0 + ls0;
        l1r = l1r * al1 + ls1;
        m0r = mn0; m1r = mn1;

        // alpha-skip: multiply-by-1.0f is bitwise identity -> skipping is
        // numerically identical.
        if (!__all_sync(0xffffffffu, (al0 == 1.f) && (al1 == 1.f))) {
#pragma unroll
            for (int j = 0; j < 16; j++) {
                o[j][0] *= al0; o[j][1] *= al0;
                o[j][2] *= al1; o[j][3] *= al1;
            }
        }

        // ---- PV ----
#pragma unroll
        for (int kk = 0; kk < 4; kk++) {
#pragma unroll
            for (int nb = 0; nb < 8; nb++) {
                uint32_t rv = swz(nb * 16 + b_rsub, kk * 32 + b_kh);
                uint32_t vh[4], vl[4];
                ldsm_x4(kvb + AVH + rv, vh[0], vh[1], vh[2], vh[3]);
                ldsm_x4(kvb + AVL + rv, vl[0], vl[1], vl[2], vl[3]);
                mma_bf16(o[2 * nb + 0], pa[kk], vh + 0);
                mma_bf16(o[2 * nb + 1], pa[kk], vh + 2);
                mma_bf16(o[2 * nb + 0], pal[kk], vh + 0);
                mma_bf16(o[2 * nb + 1], pal[kk], vh + 2);
                mma_bf16(o[2 * nb + 0], pa[kk], vl + 0);
                mma_bf16(o[2 * nb + 1], pa[kk], vl + 2);
            }
        }

        // ---- issue tile t+2 AFTER compute (R13 ordering) ----
        ATTN_ISSUE(t + 2);
        cp_commit();
    }

    // ---- epilogue: write bf16 hi/lo ----
    float inv0 = 1.f / l0r, inv1 = 1.f / l1r;
    int r0 = lane >> 2, c2 = 2 * (lane & 3);
    size_t row0 = (size_t)b * S_ + q0 + wid * 16 + r0;
#pragma unroll
    for (int j = 0; j < 16; j++) {
        int col = h * HD_ + 8 * j + c2;
        float f0 = o[j][0] * inv0, f1 = o[j][1] * inv0;
        float f2 = o[j][2] * inv1, f3 = o[j][3] * inv1;
        __nv_bfloat16 h0, l0, h1, l1, h2, l2, h3, l3;
        split1(f0, h0, l0); split1(f1, h1, l1);
        split1(f2, h2, l2); split1(f3, h3, l3);
        *(uint32_t*)&outh[row0 * HID_ + col] = pk(h0, h1);
        *(uint32_t*)&outl[row0 * HID_ + col] = pk(l0, l1);
        *(uint32_t*)&outh[(row0 + 8) * HID_ + col] = pk(h2, h3);
        *(uint32_t*)&outl[(row0 + 8) * HID_ + col] = pk(l2, l3);
    }
#undef ATTN_ISSUE
}

// ---------------------------------------------------------------------------
// kernel_launch
// ---------------------------------------------------------------------------
extern "C" void kernel_launch(void* const* d_in, const int* in_sizes, int n_in,
                              void* d_out, int out_size)
{
    const float *hidden = nullptr, *cosb = nullptr, *sinb = nullptr;
    const float *wqkv = nullptr, *bqkv = nullptr, *wo = nullptr, *bo = nullptr;
    for (int i = 0; i < n_in; i++) {
        long sz = in_sizes[i];
        const float* p = (const float*)d_in[i];
        if (sz == (long)TOK * HID_)            hidden = p;
        else if (sz == (long)S_ * 64) {
            if (!cosb) cosb = p; else sinb = p;
        }
        else if (sz == (long)HID_ * QKVN)      wqkv = p;
        else if (sz == (long)QKVN)             bqkv = p;
        else if (sz == (long)HID_ * HID_)      wo = p;
        else if (sz == (long)HID_)             bo = p;
    }
    float* out = (float*)d_out;

    __nv_bfloat16 *hid_h, *hid_l, *attn_h, *attn_l;
    __nv_bfloat16 *wqkv_h, *wqkv_l, *wo_h, *wo_l, *qkvb_h, *qkvb_l;
    __nv_bfloat16 *vt_h, *vt_l;
    cudaGetSymbolAddress((void**)&hid_h, g_hid_h);
    cudaGetSymbolAddress((void**)&hid_l, g_hid_l);
    cudaGetSymbolAddress((void**)&attn_h, g_attn_h);
    cudaGetSymbolAddress((void**)&attn_l, g_attn_l);
    cudaGetSymbolAddress((void**)&wqkv_h, g_wqkv_h);
    cudaGetSymbolAddress((void**)&wqkv_l, g_wqkv_l);
    cudaGetSymbolAddress((void**)&wo_h, g_wo_h);
    cudaGetSymbolAddress((void**)&wo_l, g_wo_l);
    cudaGetSymbolAddress((void**)&qkvb_h, g_qkvb_h);
    cudaGetSymbolAddress((void**)&qkvb_l, g_qkvb_l);
    cudaGetSymbolAddress((void**)&vt_h, g_vt_h);
    cudaGetSymbolAddress((void**)&vt_l, g_vt_l);

    cudaFuncSetAttribute(gemm3x_kernel,
                         cudaFuncAttributeMaxDynamicSharedMemorySize, GEMM_SMEM);
    cudaFuncSetAttribute(gemm_qkv_fused_kernel,
                         cudaFuncAttributeMaxDynamicSharedMemorySize, GEMM_SMEM);
    cudaFuncSetAttribute(attn_mma_kernel,
                         cudaFuncAttributeMaxDynamicSharedMemorySize, ATTN2_SMEM);

    // 0) weight + hidden pre-split
    {
        dim3 g1(QKVN / 32, HID_ / 32);
        split_wT_kernel<<<g1, 256>>>(wqkv, wqkv_h, wqkv_l, HID_, QKVN);
        dim3 g2(HID_ / 32, HID_ / 32);
        split_wT_kernel<<<g2, 256>>>(wo, wo_h, wo_l, HID_, HID_);
        size_t n4 = (size_t)TOK * HID_ / 4;
        split_a_kernel<<<(unsigned)((n4 + 255) / 256), 256>>>(hidden, hid_h, hid_l, n4);
    }
    // 1) QKV projection with fused RoPE/split/V^T epilogue
    {
        dim3 grid(QKVN / 128, TOK / 128);  // (24, 64)
        gemm_qkv_fused_kernel<<<grid, 256, GEMM_SMEM>>>(
            hid_h, hid_l, wqkv_h, wqkv_l, bqkv, cosb, sinb,
            qkvb_h, qkvb_l, vt_h, vt_l, TOK, QKVN, HID_);
    }
    // 2) Attention (cp.async 3-stage, bf16 hi/lo out)
    {
        dim3 grid(S_ / 128, NH_, B_);  // (16, 16, 4)
        attn_mma_kernel<<<grid, 256, ATTN2_SMEM>>>(qkvb_h, qkvb_l, vt_h, vt_l,
                                                   attn_h, attn_l);
    }
    // 3) Output projection (exact R13 kernel/codegen)
    {
        dim3 grid(HID_ / 128, TOK / 128);  // (16, 64)
        gemm3x_kernel<<<grid, 256, GEMM_SMEM>>>(attn_h, attn_l, wo_h, wo_l,
                                                bo, out, TOK, HID_, HID_);
    }
}

// round 17
// speedup vs baseline: 1.0252x; 1.0052x over previous
#include <cuda_runtime.h>
#include <cuda_bf16.h>
#include <cstdint>
#include <math.h>

// ---------------------------------------------------------------------------
// Problem constants: B=4, S=2048, HID=2048, NH=16, NKV=4, HD=128.
// ---------------------------------------------------------------------------
#define B_    4
#define S_    2048
#define HID_  2048
#define NH_   16
#define NKV_  4
#define HD_   128
#define QSZ   (NH_ * HD_)          // 2048
#define KVSZ  (NKV_ * HD_)         // 512
#define QKVN  (QSZ + 2 * KVSZ)     // 3072
#define TOK   (B_ * S_)            // 8192

// Scratch (device globals; no allocs allowed)
__device__ __align__(16) __nv_bfloat16  g_hid_h[(size_t)TOK * HID_];
__device__ __align__(16) __nv_bfloat16  g_hid_l[(size_t)TOK * HID_];
__device__ __align__(16) __nv_bfloat16  g_attn_h[(size_t)TOK * HID_];
__device__ __align__(16) __nv_bfloat16  g_attn_l[(size_t)TOK * HID_];
__device__ __align__(16) __nv_bfloat16  g_wqkv_h[(size_t)QKVN * HID_];  // [N][K]
__device__ __align__(16) __nv_bfloat16  g_wqkv_l[(size_t)QKVN * HID_];
__device__ __align__(16) __nv_bfloat16  g_wo_h[(size_t)HID_ * HID_];    // [N][K]
__device__ __align__(16) __nv_bfloat16  g_wo_l[(size_t)HID_ * HID_];
__device__ __align__(16) __nv_bfloat16  g_qkvb_h[(size_t)TOK * QKVN];   // rope'd q,k
__device__ __align__(16) __nv_bfloat16  g_qkvb_l[(size_t)TOK * QKVN];
// V^T pre-transposed: [b][kvh][hd][S]
__device__ __align__(16) __nv_bfloat16  g_vt_h[(size_t)B_ * NKV_ * HD_ * S_];
__device__ __align__(16) __nv_bfloat16  g_vt_l[(size_t)B_ * NKV_ * HD_ * S_];

// ---------------------------------------------------------------------------
// Helpers
// ---------------------------------------------------------------------------
__device__ __forceinline__ uint32_t smem_u32(const void* p) {
    uint32_t a;
    asm("{ .reg .u64 t; cvta.to.shared.u64 t, %1; cvt.u32.u64 %0, t; }"
        : "=r"(a) : "l"(p));
    return a;
}
__device__ __forceinline__ void ldsm_x4(uint32_t addr, uint32_t& r0, uint32_t& r1,
                                        uint32_t& r2, uint32_t& r3) {
    asm volatile("ldmatrix.sync.aligned.m8n8.x4.shared.b16 {%0,%1,%2,%3}, [%4];"
                 : "=r"(r0), "=r"(r1), "=r"(r2), "=r"(r3) : "r"(addr));
}
__device__ __forceinline__ void mma_bf16(float* d, const uint32_t* a,
                                         const uint32_t* b) {
    asm volatile(
        "mma.sync.aligned.m16n8k16.row.col.f32.bf16.bf16.f32 "
        "{%0,%1,%2,%3}, {%4,%5,%6,%7}, {%8,%9}, {%0,%1,%2,%3};"
        : "+f"(d[0]), "+f"(d[1]), "+f"(d[2]), "+f"(d[3])
        : "r"(a[0]), "r"(a[1]), "r"(a[2]), "r"(a[3]), "r"(b[0]), "r"(b[1]));
}
__device__ __forceinline__ void cp16(uint32_t d, const void* s) {
    asm volatile("cp.async.cg.shared.global [%0], [%1], 16;" :: "r"(d), "l"(s));
}
__device__ __forceinline__ void cp_commit() {
    asm volatile("cp.async.commit_group;" ::: "memory");
}
__device__ __forceinline__ void cp_wait1() {
    asm volatile("cp.async.wait_group 1;" ::: "memory");
}
__device__ __forceinline__ uint32_t pk(__nv_bfloat16 a, __nv_bfloat16 b) {
    __nv_bfloat162 t = __halves2bfloat162(a, b);
    return *reinterpret_cast<uint32_t*>(&t);
}
__device__ __forceinline__ void split1(float x, __nv_bfloat16& h, __nv_bfloat16& l) {
    h = __float2bfloat16(x);
    l = __float2bfloat16(x - __bfloat162float(h));
}
// swizzled byte offset, 128-byte rows (64 bf16)
__device__ __forceinline__ uint32_t swz(uint32_t row, uint32_t kbyte) {
    return (row * 128 + kbyte) ^ ((row & 7) << 4);
}
// swizzled byte offset, 256-byte rows (128 bf16)
__device__ __forceinline__ uint32_t swz256(uint32_t row, uint32_t kbyte) {
    return (row * 256 + kbyte) ^ ((row & 7) << 4);
}

// ---------------------------------------------------------------------------
// Merged prep kernel: split_a(hidden) + split_wT(wqkv) + split_wT(wo) in one
// launch (flat grid, block-index dispatch; bodies identical to R16 kernels).
// ---------------------------------------------------------------------------
#define NBLK_A   16384                       /* TOK*HID/4/256 */
#define NBLK_W1  ((QKVN / 32) * (HID_ / 32)) /* 6144 */
#define NBLK_W2  ((HID_ / 32) * (HID_ / 32)) /* 4096 */
#define NBLK_PREP (NBLK_A + NBLK_W1 + NBLK_W2)

__global__ __launch_bounds__(256) void prep_kernel(
    const float* __restrict__ hidden,
    __nv_bfloat16* __restrict__ hid_h, __nv_bfloat16* __restrict__ hid_l,
    const float* __restrict__ wqkv,
    __nv_bfloat16* __restrict__ wqkv_h, __nv_bfloat16* __restrict__ wqkv_l,
    const float* __restrict__ wo,
    __nv_bfloat16* __restrict__ wo_h, __nv_bfloat16* __restrict__ wo_l)
{
    __shared__ float tile[32][33];
    int bidx = blockIdx.x;

    if (bidx < NBLK_A) {
        // ---- split_a body (identical numerics) ----
        size_t i = (size_t)bidx * 256 + threadIdx.x;
        float4 v = *(const float4*)&hidden[4 * i];
        __nv_bfloat16 h0, h1, h2, h3, l0, l1, l2, l3;
        split1(v.x, h0, l0); split1(v.y, h1, l1);
        split1(v.z, h2, l2); split1(v.w, h3, l3);
        uint2 hv, lv;
        hv.x = pk(h0, h1); hv.y = pk(h2, h3);
        lv.x = pk(l0, l1); lv.y = pk(l2, l3);
        *(uint2*)&hid_h[4 * i] = hv;
        *(uint2*)&hid_l[4 * i] = lv;
        return;
    }
    bidx -= NBLK_A;

    const float* W;
    __nv_bfloat16 *WhT, *WlT;
    int N, nb, kb;
    if (bidx < NBLK_W1) {
        W = wqkv; WhT = wqkv_h; WlT = wqkv_l; N = QKVN;
        nb = (bidx % (QKVN / 32)) * 32;
        kb = (bidx / (QKVN / 32)) * 32;
    } else {
        bidx -= NBLK_W1;
        W = wo; WhT = wo_h; WlT = wo_l; N = HID_;
        nb = (bidx % (HID_ / 32)) * 32;
        kb = (bidx / (HID_ / 32)) * 32;
    }
    const int K = HID_;
    int tx = threadIdx.x & 31, ty = threadIdx.x >> 5;   // 32 x 8
#pragma unroll
    for (int r = 0; r < 4; r++)
        tile[ty + 8 * r][tx] = W[(size_t)(kb + ty + 8 * r) * N + nb + tx];
    __syncthreads();
#pragma unroll
    for (int r = 0; r < 4; r++) {
        int n = nb + ty + 8 * r, k = kb + tx;
        float x = tile[tx][ty + 8 * r];
        __nv_bfloat16 h, l;
        split1(x, h, l);
        WhT[(size_t)n * K + k] = h;
        WlT[(size_t)n * K + k] = l;
    }
}

// ---------------------------------------------------------------------------
// Shared GEMM macros (R13 mainloop)
// ---------------------------------------------------------------------------
#define GKC     64
#define STG_B   65536
#define SOFF_AH 0
#define SOFF_AL 16384
#define SOFF_BH 32768
#define SOFF_BL 49152
#define GEMM_SMEM (3 * STG_B)

#define GEMM_PROLOGUE()                                                        \
    extern __shared__ char smem[];                                             \
    const uint32_t sbase = smem_u32(smem);                                     \
    const int tid = threadIdx.x;                                               \
    const int wid = tid >> 5, lane = tid & 31;                                 \
    const int m0 = blockIdx.y * 128, n0 = blockIdx.x * 128;                    \
    const int wm = wid & 3;                                                    \
    const int wn = wid >> 2;                                                   \
    const int prow = tid >> 3;                                                 \
    const int pks  = tid & 7;                                                  \
    float acc[2][8][4];                                                        \
    _Pragma("unroll")                                                          \
    for (int i = 0; i < 2; i++)                                                \
        _Pragma("unroll")                                                      \
        for (int j = 0; j < 8; j++)                                            \
            _Pragma("unroll")                                                  \
            for (int q = 0; q < 4; q++) acc[i][j][q] = 0.f;                    \
    const int NC = K / GKC;

#define GEMM_ISSUE(c)                                                          \
    do {                                                                       \
        if ((c) < NC) {                                                        \
            uint32_t stg = sbase + ((c) % 3) * STG_B;                          \
            int kc = (c) * GKC;                                                \
            _Pragma("unroll")                                                  \
            for (int i_ = 0; i_ < 4; i_++) {                                   \
                int row = prow + 32 * i_;                                      \
                uint32_t off = swz(row, pks * 16);                             \
                size_t ao = (size_t)(m0 + row) * K + kc + pks * 8;             \
                size_t bo = (size_t)(n0 + row) * K + kc + pks * 8;             \
                cp16(stg + SOFF_AH + off, Ah + ao);                            \
                cp16(stg + SOFF_AL + off, Al + ao);                            \
                cp16(stg + SOFF_BH + off, BhT + bo);                           \
                cp16(stg + SOFF_BL + off, BlT + bo);                           \
            }                                                                  \
        }                                                                      \
    } while (0)

#define GEMM_MAINLOOP()                                                        \
    GEMM_ISSUE(0); cp_commit();                                                \
    GEMM_ISSUE(1); cp_commit();                                                \
    const int a_row = wm * 32 + (lane & 15);                                   \
    const int a_kh  = (lane >> 4) << 4;                                        \
    const int b_row = wn * 64 + ((lane >> 4) << 3) + (lane & 7);               \
    const int b_kh  = ((lane >> 3) & 1) << 4;                                  \
    for (int c = 0; c < NC; c++) {                                             \
        cp_wait1();                                                            \
        __syncthreads();                                                       \
        const uint32_t sb = sbase + (c % 3) * STG_B;                           \
        _Pragma("unroll")                                                      \
        for (int s = 0; s < 4; s++) {                                          \
            const uint32_t kbyte = 32 * s;                                     \
            uint32_t ah[2][4], al[2][4];                                       \
            _Pragma("unroll")                                                  \
            for (int ti = 0; ti < 2; ti++) {                                   \
                uint32_t ra = swz(a_row + 16 * ti, kbyte + a_kh);              \
                ldsm_x4(sb + SOFF_AH + ra, ah[ti][0], ah[ti][1], ah[ti][2], ah[ti][3]); \
                ldsm_x4(sb + SOFF_AL + ra, al[ti][0], al[ti][1], al[ti][2], al[ti][3]); \
            }                                                                  \
            _Pragma("unroll")                                                  \
            for (int pj = 0; pj < 4; pj++) {                                   \
                uint32_t rb = swz(b_row + 16 * pj, kbyte + b_kh);              \
                uint32_t bh[4], bl[4];                                         \
                ldsm_x4(sb + SOFF_BH + rb, bh[0], bh[1], bh[2], bh[3]);        \
                ldsm_x4(sb + SOFF_BL + rb, bl[0], bl[1], bl[2], bl[3]);        \
                _Pragma("unroll")                                              \
                for (int ti = 0; ti < 2; ti++) {                               \
                    mma_bf16(acc[ti][2 * pj + 0], ah[ti], bh + 0);             \
                    mma_bf16(acc[ti][2 * pj + 1], ah[ti], bh + 2);             \
                    mma_bf16(acc[ti][2 * pj + 0], ah[ti], bl + 0);             \
                    mma_bf16(acc[ti][2 * pj + 1], ah[ti], bl + 2);             \
                    mma_bf16(acc[ti][2 * pj + 0], al[ti], bh + 0);             \
                    mma_bf16(acc[ti][2 * pj + 1], al[ti], bh + 2);             \
                }                                                              \
            }                                                                  \
        }                                                                      \
        GEMM_ISSUE(c + 2);                                                     \
        cp_commit();                                                           \
    }

// ---------------------------------------------------------------------------
// bf16x3 mma.sync GEMM — EXACT R13 (plain fp32 epilogue; out-projection).
// ---------------------------------------------------------------------------
__global__ __launch_bounds__(256, 1) void gemm3x_kernel(
    const __nv_bfloat16* __restrict__ Ah, const __nv_bfloat16* __restrict__ Al,
    const __nv_bfloat16* __restrict__ BhT, const __nv_bfloat16* __restrict__ BlT,
    const float* __restrict__ bias, float* __restrict__ C,
    int M, int N, int K)
{
    GEMM_PROLOGUE();
    GEMM_MAINLOOP();

#pragma unroll
    for (int tj = 0; tj < 8; tj++) {
        int col = n0 + wn * 64 + tj * 8 + 2 * (lane & 3);
        float2 bb = *(const float2*)&bias[col];
#pragma unroll
        for (int ti = 0; ti < 2; ti++) {
            int row = m0 + wm * 32 + ti * 16 + (lane >> 2);
            float2 v0, v1;
            v0.x = acc[ti][tj][0] + bb.x; v0.y = acc[ti][tj][1] + bb.y;
            v1.x = acc[ti][tj][2] + bb.x; v1.y = acc[ti][tj][3] + bb.y;
            *(float2*)&C[(size_t)row * N + col] = v0;
            *(float2*)&C[(size_t)(row + 8) * N + col] = v1;
        }
    }
}

// ---------------------------------------------------------------------------
// QKV GEMM with fused RoPE/split/V^T epilogue (R16 exact).
// ---------------------------------------------------------------------------
__global__ __launch_bounds__(256, 1) void gemm_qkv_fused_kernel(
    const __nv_bfloat16* __restrict__ Ah, const __nv_bfloat16* __restrict__ Al,
    const __nv_bfloat16* __restrict__ BhT, const __nv_bfloat16* __restrict__ BlT,
    const float* __restrict__ bias,
    const float* __restrict__ cosb, const float* __restrict__ sinb,
    __nv_bfloat16* __restrict__ oh, __nv_bfloat16* __restrict__ ol,
    __nv_bfloat16* __restrict__ vth, __nv_bfloat16* __restrict__ vtl,
    int M, int N, int K)
{
    GEMM_PROLOGUE();
    GEMM_MAINLOOP();

    // ---- fused QKV epilogue ----
    __syncthreads();   // all warps done with pipeline smem
    float* Cs = (float*)smem;   // [128][129] fp32, 66KB

#pragma unroll
    for (int tj = 0; tj < 8; tj++) {
        int col = wn * 64 + tj * 8 + 2 * (lane & 3);
        float2 bb = *(const float2*)&bias[n0 + col];
#pragma unroll
        for (int ti = 0; ti < 2; ti++) {
            int row = wm * 32 + ti * 16 + (lane >> 2);
            Cs[row * 129 + col]     = acc[ti][tj][0] + bb.x;
            Cs[row * 129 + col + 1] = acc[ti][tj][1] + bb.y;
            Cs[(row + 8) * 129 + col]     = acc[ti][tj][2] + bb.x;
            Cs[(row + 8) * 129 + col + 1] = acc[ti][tj][3] + bb.y;
        }
    }
    __syncthreads();

    if (n0 < QSZ + KVSZ) {
        // q/k tile: RoPE + split
        const int dcol = (tid & 31) * 2;       // 0..62
        const int rbase = tid >> 5;            // 0..7
#pragma unroll
        for (int it = 0; it < 16; it++) {
            int r = it * 8 + rbase;
            int tok = m0 + r;
            int s = tok & (S_ - 1);
            float x1a = Cs[r * 129 + dcol];
            float x1b = Cs[r * 129 + dcol + 1];
            float x2a = Cs[r * 129 + dcol + 64];
            float x2b = Cs[r * 129 + dcol + 65];
            float2 c2v = *(const float2*)&cosb[s * 64 + dcol];
            float2 s2v = *(const float2*)&sinb[s * 64 + dcol];
            float y1a = x1a * c2v.x - x2a * s2v.x;
            float y1b = x1b * c2v.y - x2b * s2v.y;
            float y2a = x2a * c2v.x + x1a * s2v.x;
            float y2b = x2b * c2v.y + x1b * s2v.y;
            size_t base = (size_t)tok * QKVN + n0 + dcol;
            __nv_bfloat16 h0, l0, h1, l1;
            split1(y1a, h0, l0); split1(y1b, h1, l1);
            *(uint32_t*)&oh[base] = pk(h0, h1);
            *(uint32_t*)&ol[base] = pk(l0, l1);
            split1(y2a, h0, l0); split1(y2b, h1, l1);
            *(uint32_t*)&oh[base + 64] = pk(h0, h1);
            *(uint32_t*)&ol[base + 64] = pk(l0, l1);
        }
    } else {
        // v tile: transpose + split
        int kvh = (n0 - QSZ - KVSZ) >> 7;      // 0..3
        int bb_ = m0 >> 11;                     // batch index (m0 / S_)
        int s_base = m0 & (S_ - 1);
        size_t vbase = ((size_t)(bb_ * NKV_ + kvh)) * HD_ * S_;
        const int sp = (tid & 63) * 2;          // s pair base 0..126
        const int dbase = tid >> 6;             // 0..3
#pragma unroll
        for (int it = 0; it < 32; it++) {
            int dv = dbase + 4 * it;            // 0..127
            float v0 = Cs[sp * 129 + dv];
            float v1 = Cs[(sp + 1) * 129 + dv];
            __nv_bfloat16 h0, l0, h1, l1;
            split1(v0, h0, l0); split1(v1, h1, l1);
            size_t o = vbase + (size_t)dv * S_ + s_base + sp;
            *(uint32_t*)&vth[o] = pk(h0, h1);
            *(uint32_t*)&vtl[o] = pk(l0, l1);
        }
    }
}

// ---------------------------------------------------------------------------
// Tensor-core flash attention — EXACT R13/R16 (cp.async 3-stage, Q in regs,
// issue AFTER PV, alpha-skip, bf16 hi/lo epilogue).
// ---------------------------------------------------------------------------
#define ASTG  65536
#define AKH   0
#define AKL   16384
#define AVH   32768
#define AVL   49152
#define ATTN2_SMEM (3 * ASTG)

__global__ __launch_bounds__(256, 1) void attn_mma_kernel(
    const __nv_bfloat16* __restrict__ qh, const __nv_bfloat16* __restrict__ ql,
    const __nv_bfloat16* __restrict__ vth, const __nv_bfloat16* __restrict__ vtl,
    __nv_bfloat16* __restrict__ outh, __nv_bfloat16* __restrict__ outl)
{
    extern __shared__ char sm[];
    const uint32_t sb = smem_u32(sm);
    const int tid = threadIdx.x;
    const int wid = tid >> 5, lane = tid & 31;
    const int q0 = blockIdx.x * 128;
    const int h  = blockIdx.y;
    const int b  = blockIdx.z;
    const int kvh = h >> 2;

    const float scale = 0.08838834764831845f;   // 1/sqrt(128)
    const size_t tok0 = (size_t)b * S_;
    const __nv_bfloat16* qbh = qh + (tok0 + q0) * QKVN + h * HD_;
    const __nv_bfloat16* qbl = ql + (tok0 + q0) * QKVN + h * HD_;
    const __nv_bfloat16* kbh = qh + tok0 * QKVN + QSZ + kvh * HD_;
    const __nv_bfloat16* kbl = ql + tok0 * QKVN + QSZ + kvh * HD_;
    const __nv_bfloat16* vbh = vth + (size_t)(b * NKV_ + kvh) * HD_ * S_;
    const __nv_bfloat16* vbl = vtl + (size_t)(b * NKV_ + kvh) * HD_ * S_;

    const int NT = S_ / 64;   // 32

    const int krow = tid >> 4, kks = tid & 15;   // K: 64 rows x 16 units (256B)
    const int vrow = tid >> 3, vks = tid & 7;    // V^T: 128 rows x 8 units (128B)

#define ATTN_ISSUE(t)                                                          \
    do {                                                                       \
        if ((t) < NT) {                                                        \
            uint32_t stg = sb + ((t) % 3) * ASTG;                              \
            size_t tb = (size_t)(t) * 64;                                      \
            _Pragma("unroll")                                                  \
            for (int i_ = 0; i_ < 4; i_++) {                                   \
                int rk = krow + 16 * i_;                                       \
                uint32_t ko = swz256(rk, kks * 16);                            \
                size_t kg = (tb + rk) * QKVN + kks * 8;                        \
                cp16(stg + AKH + ko, kbh + kg);                                \
                cp16(stg + AKL + ko, kbl + kg);                                \
                int rv = vrow + 32 * i_;                                       \
                uint32_t vo = swz(rv, vks * 16);                               \
                size_t vg = (size_t)rv * S_ + tb + vks * 8;                    \
                cp16(stg + AVH + vo, vbh + vg);                                \
                cp16(stg + AVL + vo, vbl + vg);                                \
            }                                                                  \
        }                                                                      \
    } while (0)

    // ---- prologue: Q into stage 0 region (hi at +0, lo at +32KB) ----
#pragma unroll
    for (int i = 0; i < 8; i++) {
        int u = tid + 256 * i;
        int row = u >> 4, ks = u & 15;
        uint32_t off = swz256(row, ks * 16);
        *(uint4*)(sm + off)         = *(const uint4*)&qbh[(size_t)row * QKVN + ks * 8];
        *(uint4*)(sm + 32768 + off) = *(const uint4*)&qbl[(size_t)row * QKVN + ks * 8];
    }
    __syncthreads();

    const int a_row = wid * 16 + (lane & 15);
    const int a_kh  = (lane >> 4) << 4;
    uint32_t qfh[8][4], qfl[8][4];
#pragma unroll
    for (int s = 0; s < 8; s++) {
        uint32_t ra = swz256(a_row, s * 32 + a_kh);
        ldsm_x4(sb + ra,         qfh[s][0], qfh[s][1], qfh[s][2], qfh[s][3]);
        ldsm_x4(sb + 32768 + ra, qfl[s][0], qfl[s][1], qfl[s][2], qfl[s][3]);
    }
    __syncthreads();

    ATTN_ISSUE(0); cp_commit();
    ATTN_ISSUE(1); cp_commit();

    float o[16][4];
#pragma unroll
    for (int j = 0; j < 16; j++)
#pragma unroll
        for (int q = 0; q < 4; q++) o[j][q] = 0.f;
    float m0r = -1e30f, m1r = -1e30f, l0r = 0.f, l1r = 0.f;

    const int b_rsub = ((lane >> 4) << 3) + (lane & 7);
    const int b_kh   = ((lane >> 3) & 1) << 4;

    for (int t = 0; t < NT; t++) {
        cp_wait1();
        __syncthreads();

        const uint32_t kvb = sb + (t % 3) * ASTG;

        // ---- QK^T (Q from registers) ----
        float sc[8][4];
#pragma unroll
        for (int j = 0; j < 8; j++)
#pragma unroll
            for (int q = 0; q < 4; q++) sc[j][q] = 0.f;

#pragma unroll
        for (int s = 0; s < 8; s++) {
#pragma unroll
            for (int nb = 0; nb < 4; nb++) {
                uint32_t rb = swz256(nb * 16 + b_rsub, s * 32 + b_kh);
                uint32_t bh[4], bl[4];
                ldsm_x4(kvb + AKH + rb, bh[0], bh[1], bh[2], bh[3]);
                ldsm_x4(kvb + AKL + rb, bl[0], bl[1], bl[2], bl[3]);
                mma_bf16(sc[2 * nb + 0], qfh[s], bh + 0);
                mma_bf16(sc[2 * nb + 1], qfh[s], bh + 2);
                mma_bf16(sc[2 * nb + 0], qfh[s], bl + 0);
                mma_bf16(sc[2 * nb + 1], qfh[s], bl + 2);
                mma_bf16(sc[2 * nb + 0], qfl[s], bh + 0);
                mma_bf16(sc[2 * nb + 1], qfl[s], bh + 2);
            }
        }

        // ---- online softmax ----
        float mx0 = -1e30f, mx1 = -1e30f;
#pragma unroll
        for (int j = 0; j < 8; j++) {
            sc[j][0] *= scale; sc[j][1] *= scale;
            sc[j][2] *= scale; sc[j][3] *= scale;
            mx0 = fmaxf(mx0, fmaxf(sc[j][0], sc[j][1]));
            mx1 = fmaxf(mx1, fmaxf(sc[j][2], sc[j][3]));
        }
        mx0 = fmaxf(mx0, __shfl_xor_sync(0xffffffffu, mx0, 1));
        mx0 = fmaxf(mx0, __shfl_xor_sync(0xffffffffu, mx0, 2));
        mx1 = fmaxf(mx1, __shfl_xor_sync(0xffffffffu, mx1, 1));
        mx1 = fmaxf(mx1, __shfl_xor_sync(0xffffffffu, mx1, 2));
        float mn0 = fmaxf(m0r, mx0), mn1 = fmaxf(m1r, mx1);
        float al0 = __expf(m0r - mn0), al1 = __expf(m1r - mn1);

        float ls0 = 0.f, ls1 = 0.f;
        uint32_t pa[4][4], pal[4][4];
#pragma unroll
        for (int j = 0; j < 8; j++) {
            float p00 = __expf(sc[j][0] - mn0);
            float p01 = __expf(sc[j][1] - mn0);
            float p10 = __expf(sc[j][2] - mn1);
            float p11 = __expf(sc[j][3] - mn1);
            ls0 += p00 + p01; ls1 += p10 + p11;
            __nv_bfloat16 h00, l00, h01, l01, h10, l10, h11, l11;
            split1(p00, h00, l00); split1(p01, h01, l01);
            split1(p10, h10, l10); split1(p11, h11, l11);
            int kk = j >> 1, hf = (j & 1) << 1;
            pa[kk][hf + 0] = pk(h00, h01);
            pa[kk][hf + 1] = pk(h10, h11);
            pal[kk][hf + 0] = pk(l00, l01);
            pal[kk][hf + 1] = pk(l10, l11);
        }
        ls0 += __shfl_xor_sync(0xffffffffu, ls0, 1);
        ls0 += __shfl_xor_sync(0xffffffffu, ls0, 2);
        ls1 += __shfl_xor_sync(0xffffffffu, ls1, 1);
        ls1 += __shfl_xor_sync(0xffffffffu, ls1, 2);
        l0r = l0r * al0 + ls0;
        l1r = l1r * al1 + ls1;
        m0r = mn0; m1r = mn1;

        // alpha-skip: multiply-by-1.0f is bitwise identity -> skipping is
        // numerically identical.
        if (!__all_sync(0xffffffffu, (al0 == 1.f) && (al1 == 1.f))) {
#pragma unroll
            for (int j = 0; j < 16; j++) {
                o[j][0] *= al0; o[j][1] *= al0;
                o[j][2] *= al1; o[j][3] *= al1;
            }
        }

        // ---- PV ----
#pragma unroll
        for (int kk = 0; kk < 4; kk++) {
#pragma unroll
            for (int nb = 0; nb < 8; nb++) {
                uint32_t rv = swz(nb * 16 + b_rsub, kk * 32 + b_kh);
                uint32_t vh[4], vl[4];
                ldsm_x4(kvb + AVH + rv, vh[0], vh[1], vh[2], vh[3]);
                ldsm_x4(kvb + AVL + rv, vl[0], vl[1], vl[2], vl[3]);
                mma_bf16(o[2 * nb + 0], pa[kk], vh + 0);
                mma_bf16(o[2 * nb + 1], pa[kk], vh + 2);
                mma_bf16(o[2 * nb + 0], pal[kk], vh + 0);
                mma_bf16(o[2 * nb + 1], pal[kk], vh + 2);
                mma_bf16(o[2 * nb + 0], pa[kk], vl + 0);
                mma_bf16(o[2 * nb + 1], pa[kk], vl + 2);
            }
        }

        // ---- issue tile t+2 AFTER compute (R13 ordering) ----
        ATTN_ISSUE(t + 2);
        cp_commit();
    }

    // ---- epilogue: write bf16 hi/lo ----
    float inv0 = 1.f / l0r, inv1 = 1.f / l1r;
    int r0 = lane >> 2, c2 = 2 * (lane & 3);
    size_t row0 = (size_t)b * S_ + q0 + wid * 16 + r0;
#pragma unroll
    for (int j = 0; j < 16; j++) {
        int col = h * HD_ + 8 * j + c2;
        float f0 = o[j][0] * inv0, f1 = o[j][1] * inv0;
        float f2 = o[j][2] * inv1, f3 = o[j][3] * inv1;
        __nv_bfloat16 h0, l0, h1, l1, h2, l2, h3, l3;
        split1(f0, h0, l0); split1(f1, h1, l1);
        split1(f2, h2, l2); split1(f3, h3, l3);
        *(uint32_t*)&outh[row0 * HID_ + col] = pk(h0, h1);
        *(uint32_t*)&outl[row0 * HID_ + col] = pk(l0, l1);
        *(uint32_t*)&outh[(row0 + 8) * HID_ + col] = pk(h2, h3);
        *(uint32_t*)&outl[(row0 + 8) * HID_ + col] = pk(l2, l3);
    }
#undef ATTN_ISSUE
}

// ---------------------------------------------------------------------------
// kernel_launch
// ---------------------------------------------------------------------------
extern "C" void kernel_launch(void* const* d_in, const int* in_sizes, int n_in,
                              void* d_out, int out_size)
{
    const float *hidden = nullptr, *cosb = nullptr, *sinb = nullptr;
    const float *wqkv = nullptr, *bqkv = nullptr, *wo = nullptr, *bo = nullptr;
    for (int i = 0; i < n_in; i++) {
        long sz = in_sizes[i];
        const float* p = (const float*)d_in[i];
        if (sz == (long)TOK * HID_)            hidden = p;
        else if (sz == (long)S_ * 64) {
            if (!cosb) cosb = p; else sinb = p;
        }
        else if (sz == (long)HID_ * QKVN)      wqkv = p;
        else if (sz == (long)QKVN)             bqkv = p;
        else if (sz == (long)HID_ * HID_)      wo = p;
        else if (sz == (long)HID_)             bo = p;
    }
    float* out = (float*)d_out;

    __nv_bfloat16 *hid_h, *hid_l, *attn_h, *attn_l;
    __nv_bfloat16 *wqkv_h, *wqkv_l, *wo_h, *wo_l, *qkvb_h, *qkvb_l;
    __nv_bfloat16 *vt_h, *vt_l;
    cudaGetSymbolAddress((void**)&hid_h, g_hid_h);
    cudaGetSymbolAddress((void**)&hid_l, g_hid_l);
    cudaGetSymbolAddress((void**)&attn_h, g_attn_h);
    cudaGetSymbolAddress((void**)&attn_l, g_attn_l);
    cudaGetSymbolAddress((void**)&wqkv_h, g_wqkv_h);
    cudaGetSymbolAddress((void**)&wqkv_l, g_wqkv_l);
    cudaGetSymbolAddress((void**)&wo_h, g_wo_h);
    cudaGetSymbolAddress((void**)&wo_l, g_wo_l);
    cudaGetSymbolAddress((void**)&qkvb_h, g_qkvb_h);
    cudaGetSymbolAddress((void**)&qkvb_l, g_qkvb_l);
    cudaGetSymbolAddress((void**)&vt_h, g_vt_h);
    cudaGetSymbolAddress((void**)&vt_l, g_vt_l);

    cudaFuncSetAttribute(gemm3x_kernel,
                         cudaFuncAttributeMaxDynamicSharedMemorySize, GEMM_SMEM);
    cudaFuncSetAttribute(gemm_qkv_fused_kernel,
                         cudaFuncAttributeMaxDynamicSharedMemorySize, GEMM_SMEM);
    cudaFuncSetAttribute(attn_mma_kernel,
                         cudaFuncAttributeMaxDynamicSharedMemorySize, ATTN2_SMEM);

    // 0) merged prep: hidden split + both weight transposes/splits, one launch
    {
        prep_kernel<<<NBLK_PREP, 256>>>(hidden, hid_h, hid_l,
                                        wqkv, wqkv_h, wqkv_l,
                                        wo, wo_h, wo_l);
    }
    // 1) QKV projection with fused RoPE/split/V^T epilogue
    {
        dim3 grid(QKVN / 128, TOK / 128);  // (24, 64)
        gemm_qkv_fused_kernel<<<grid, 256, GEMM_SMEM>>>(
            hid_h, hid_l, wqkv_h, wqkv_l, bqkv, cosb, sinb,
            qkvb_h, qkvb_l, vt_h, vt_l, TOK, QKVN, HID_);
    }
    // 2) Attention (cp.async 3-stage, bf16 hi/lo out)
    {
        dim3 grid(S_ / 128, NH_, B_);  // (16, 16, 4)
        attn_mma_kernel<<<grid, 256, ATTN2_SMEM>>>(qkvb_h, qkvb_l, vt_h, vt_l,
                                                   attn_h, attn_l);
    }
    // 3) Output projection (exact R13 kernel/codegen)
    {
        dim3 grid(HID_ / 128, TOK / 128);  // (16, 64)
        gemm3x_kernel<<<grid, 256, GEMM_SMEM>>>(attn_h, attn_l, wo_h, wo_l,
                                                bo, out, TOK, HID_, HID_);
    }
}